// round 15
// baseline (speedup 1.0000x reference)
#include <cuda_runtime.h>
#include <cuda_fp16.h>
#include <math.h>
#include <stdint.h>

#define BSZ   4
#define NPT   8192
#define CH    256
#define NPTS  (BSZ*NPT)      // 32768
#define QKVW  768
#define PGRID 296            // persistent grid: 148 SMs x 2 CTAs

// -------------------- scratch (device globals; no cudaMalloc allowed) -----
__device__ __half g_h[NPTS*CH];          // LN out
__device__ __half g_qkvh[NPTS*QKVW];
__device__ __half g_av[NPTS*CH];         // attn-weighted V
__device__ __half g_u[NPTS*1024];        // pe basis U: [p][h][256]
__device__ __half g_s[NPTS*CH];          // av + pe (proj GEMM input)
__device__ float  g_x[NPTS*CH];          // residual stream
__device__ __half g_mlp1[NPTS*1024];
__device__ __half g_wqkvT[QKVW*CH];      // [768][256]   Bt (N,K)
__device__ __half g_wm1T[1024*CH];       // [1024][256]
__device__ __half g_wm2T[CH*1024];       // [256][1024]
__device__ __half g_wprojT[CH*CH];       // [256][256]
__device__ __half g_wd2T[CH*CH];         // wd2T[n][k] = w_d2[k][n]
__device__ float  g_bfold[CH];           // b_proj + b_d2 @ w_proj

// ==================== prologue: tiled transposes + bfold ==================
__global__ void prologue_all(const float* __restrict__ w_qkv,
                             const float* __restrict__ w_m1,
                             const float* __restrict__ w_m2,
                             const float* __restrict__ w_proj,
                             const float* __restrict__ w_d2,
                             const float* __restrict__ b_d2,
                             const float* __restrict__ b_proj,
                             __half* __restrict__ qkvT, __half* __restrict__ m1T,
                             __half* __restrict__ m2T,  __half* __restrict__ projT,
                             __half* __restrict__ d2T,  float* __restrict__ bfold)
{
    int z = blockIdx.z;
    if (z == 5) {
        if (blockIdx.x || blockIdx.y) return;
        int c = threadIdx.y * 32 + threadIdx.x;   // 0..255
        float acc = b_proj[c];
        #pragma unroll 8
        for (int cc = 0; cc < CH; cc++)
            acc = fmaf(b_d2[cc], w_proj[cc*CH + c], acc);
        bfold[c] = acc;
        return;
    }
    const float* src; __half* dst; int R, C;
    switch (z) {
        case 0: src = w_qkv;  dst = qkvT;  R = 256;  C = 768;  break;
        case 1: src = w_m1;   dst = m1T;   R = 256;  C = 1024; break;
        case 2: src = w_m2;   dst = m2T;   R = 1024; C = 256;  break;
        case 3: src = w_proj; dst = projT; R = 256;  C = 256;  break;
        default:src = w_d2;   dst = d2T;   R = 256;  C = 256;  break;
    }
    int bx = blockIdx.x * 32, by = blockIdx.y * 32;
    if (bx >= C || by >= R) return;
    __shared__ float t[32][33];
    #pragma unroll
    for (int j = 0; j < 32; j += 8)
        t[threadIdx.y + j][threadIdx.x] =
            src[(size_t)(by + threadIdx.y + j) * C + bx + threadIdx.x];
    __syncthreads();
    #pragma unroll
    for (int j = 0; j < 32; j += 8)
        dst[(size_t)(bx + threadIdx.y + j) * R + by + threadIdx.x] =
            __float2half(t[threadIdx.x][threadIdx.y + j]);
}

// -------------------- LayerNorm (warp per row) ----------------------------
__global__ void __launch_bounds__(256)
ln_kernel(const float* __restrict__ x, const float* __restrict__ g,
          const float* __restrict__ b, __half* __restrict__ out)
{
    int warp = threadIdx.x >> 5, lane = threadIdx.x & 31;
    int row  = blockIdx.x * 8 + warp;
    const float* xr = x + (size_t)row*CH + lane*8;

    float v[8];
    *(float4*)(v)     = *(const float4*)(xr);
    *(float4*)(v + 4) = *(const float4*)(xr + 4);

    float s = 0.f;
    #pragma unroll
    for (int j = 0; j < 8; j++) s += v[j];
    #pragma unroll
    for (int o = 16; o > 0; o >>= 1) s += __shfl_xor_sync(0xffffffffu, s, o);
    float mean = s * (1.0f / CH);

    float d[8], ss = 0.f;
    #pragma unroll
    for (int j = 0; j < 8; j++) { d[j] = v[j] - mean; ss += d[j]*d[j]; }
    #pragma unroll
    for (int o = 16; o > 0; o >>= 1) ss += __shfl_xor_sync(0xffffffffu, ss, o);
    float rstd = rsqrtf(ss * (1.0f / CH) + 1e-5f);

    float gv[8], bv[8];
    *(float4*)(gv)     = *(const float4*)(g + lane*8);
    *(float4*)(gv + 4) = *(const float4*)(g + lane*8 + 4);
    *(float4*)(bv)     = *(const float4*)(b + lane*8);
    *(float4*)(bv + 4) = *(const float4*)(b + lane*8 + 4);

    __half2 o2[4];
    #pragma unroll
    for (int j = 0; j < 4; j++)
        o2[j] = __floats2half2_rn(d[2*j]*rstd*gv[2*j] + bv[2*j],
                                  d[2*j+1]*rstd*gv[2*j+1] + bv[2*j+1]);
    *(uint4*)(out + (size_t)row*CH + lane*8) = *(uint4*)o2;
}

// ------------ fp16 tensor-core GEMM (128x128x32, 4-stage, persistent) -----
__device__ __forceinline__ float gelu_exact(float v) { return v * normcdff(v); }

#define HBM 128
#define HBN 128
#define HBK 32
#define AS_STR 40                            // HBK + 8 halves (80 B rows)
#define STAGE_H ((HBM + HBN) * AS_STR)       // 10240 halves per stage
#define HSMEM_BYTES (4*STAGE_H*2)            // 81920 B (4 stages)

__device__ __forceinline__ void mma16816(float* c, const uint32_t* a,
                                         uint32_t b0, uint32_t b1)
{
    asm volatile(
        "mma.sync.aligned.m16n8k16.row.col.f32.f16.f16.f32 "
        "{%0,%1,%2,%3}, {%4,%5,%6,%7}, {%8,%9}, {%0,%1,%2,%3};"
        : "+f"(c[0]), "+f"(c[1]), "+f"(c[2]), "+f"(c[3])
        : "r"(a[0]), "r"(a[1]), "r"(a[2]), "r"(a[3]), "r"(b0), "r"(b1));
}

template<int EPI, typename OutT>
__global__ void __launch_bounds__(256, 2)
hgemm(const __half* __restrict__ A, const __half* __restrict__ B,
      OutT* __restrict__ C, int M, int N, int K,
      const float* __restrict__ bias, const float* __restrict__ resid)
{
    extern __shared__ __half sh[];

    int tid  = threadIdx.x;
    int lane = tid & 31;
    int warp = tid >> 5;
    int wm   = warp & 1;
    int wn   = warp >> 1;

    int nbx = N / HBN;
    int ntiles = (M / HBM) * nbx;
    int nt = K / HBK;

    for (int t = blockIdx.x; t < ntiles; t += gridDim.x) {
        int bm = (t / nbx) * HBM;
        int bn = (t % nbx) * HBN;
        const __half* Ag = A + (size_t)bm * K;
        const __half* Bg = B + (size_t)bn * K;      // Bt layout [N][K]

        float acc[4][4][4];
        #pragma unroll
        for (int i = 0; i < 4; i++)
            #pragma unroll
            for (int j = 0; j < 4; j++)
                #pragma unroll
                for (int r = 0; r < 4; r++) acc[i][j][r] = 0.f;

        auto issue = [&](int kt, int buf) {
            __half* As = sh + buf * STAGE_H;
            __half* Bs = As + HBM * AS_STR;
            #pragma unroll
            for (int s = 0; s < 2; s++) {
                int c  = tid * 2 + s;
                int ar = c >> 2, ak = (c & 3) * 8;
                uint32_t da = (uint32_t)__cvta_generic_to_shared(As + ar*AS_STR + ak);
                const __half* ga = Ag + (size_t)ar * K + kt * HBK + ak;
                asm volatile("cp.async.cg.shared.global [%0], [%1], 16;\n"
                             :: "r"(da), "l"(ga));
                uint32_t db = (uint32_t)__cvta_generic_to_shared(Bs + ar*AS_STR + ak);
                const __half* gb = Bg + (size_t)ar * K + kt * HBK + ak;
                asm volatile("cp.async.cg.shared.global [%0], [%1], 16;\n"
                             :: "r"(db), "l"(gb));
            }
            asm volatile("cp.async.commit_group;\n");
        };

        issue(0, 0);
        issue(1, 1);
        issue(2, 2);
        asm volatile("cp.async.wait_group 2;\n");
        __syncthreads();

        for (int kt = 0; kt < nt; kt++) {
            int cur = kt & 3;
            if (kt + 3 < nt) issue(kt + 3, (kt + 3) & 3);

            __half* As = sh + cur * STAGE_H;
            __half* Bs = As + HBM * AS_STR;

            #pragma unroll
            for (int kk = 0; kk < HBK; kk += 16) {
                uint32_t af[4][4], bf[2][4];
                #pragma unroll
                for (int i = 0; i < 4; i++) {
                    int row = wm * 64 + i * 16 + (lane & 15);
                    int kc  = kk + (lane >> 4) * 8;
                    uint32_t ad = (uint32_t)__cvta_generic_to_shared(As + row*AS_STR + kc);
                    asm volatile(
                        "ldmatrix.sync.aligned.m8n8.x4.shared.b16 {%0,%1,%2,%3}, [%4];"
                        : "=r"(af[i][0]), "=r"(af[i][1]), "=r"(af[i][2]), "=r"(af[i][3])
                        : "r"(ad));
                }
                #pragma unroll
                for (int j = 0; j < 2; j++) {
                    int nrow = wn * 32 + j * 16 + (lane & 15);
                    int kc   = kk + (lane >> 4) * 8;
                    uint32_t bd = (uint32_t)__cvta_generic_to_shared(Bs + nrow*AS_STR + kc);
                    asm volatile(
                        "ldmatrix.sync.aligned.m8n8.x4.shared.b16 {%0,%1,%2,%3}, [%4];"
                        : "=r"(bf[j][0]), "=r"(bf[j][1]), "=r"(bf[j][2]), "=r"(bf[j][3])
                        : "r"(bd));
                }
                #pragma unroll
                for (int j = 0; j < 2; j++)
                    #pragma unroll
                    for (int i = 0; i < 4; i++) {
                        mma16816(acc[i][2*j],     af[i], bf[j][0], bf[j][2]);
                        mma16816(acc[i][2*j + 1], af[i], bf[j][1], bf[j][3]);
                    }
            }

            if (kt + 3 < nt)      { asm volatile("cp.async.wait_group 2;\n"); __syncthreads(); }
            else if (kt + 2 < nt) { asm volatile("cp.async.wait_group 1;\n"); __syncthreads(); }
            else if (kt + 1 < nt) { asm volatile("cp.async.wait_group 0;\n"); __syncthreads(); }
        }
        // drain any residual async groups, and fence smem for next tile
        asm volatile("cp.async.wait_group 0;\n");
        __syncthreads();

        #pragma unroll
        for (int i = 0; i < 4; i++) {
            int row = bm + wm * 64 + i * 16 + (lane >> 2);
            #pragma unroll
            for (int jj = 0; jj < 4; jj++) {
                int col = bn + wn * 32 + (jj >> 1) * 16 + (jj & 1) * 8 + (lane & 3) * 2;
                float2 v0 = make_float2(acc[i][jj][0], acc[i][jj][1]);
                float2 v1 = make_float2(acc[i][jj][2], acc[i][jj][3]);
                if (EPI >= 1) {
                    float2 bv = *(const float2*)&bias[col];
                    v0.x += bv.x; v0.y += bv.y;
                    v1.x += bv.x; v1.y += bv.y;
                }
                if (EPI == 1) {
                    float2 r0 = *(const float2*)&resid[(size_t)row * N + col];
                    float2 r1 = *(const float2*)&resid[(size_t)(row + 8) * N + col];
                    v0.x += r0.x; v0.y += r0.y;
                    v1.x += r1.x; v1.y += r1.y;
                }
                if (EPI == 2) {
                    v0.x = gelu_exact(v0.x); v0.y = gelu_exact(v0.y);
                    v1.x = gelu_exact(v1.x); v1.y = gelu_exact(v1.y);
                }
                if constexpr (sizeof(OutT) == 2) {
                    *(__half2*)&C[(size_t)row * N + col]       = __floats2half2_rn(v0.x, v0.y);
                    *(__half2*)&C[(size_t)(row + 8) * N + col] = __floats2half2_rn(v1.x, v1.y);
                } else {
                    *(float2*)&C[(size_t)row * N + col]       = v0;
                    *(float2*)&C[(size_t)(row + 8) * N + col] = v1;
                }
            }
        }
    }
}

// ==================== pe GEMM: s = av + U_h @ w_d2[:, h-slice] ============
#define PE_ASTR 40
__global__ void __launch_bounds__(256, 2)
pe_gemm(const __half* __restrict__ U, const __half* __restrict__ wd2T,
        const __half* __restrict__ av, __half* __restrict__ s)
{
    __shared__ __half sp[3 * 192 * PE_ASTR];

    int tid  = threadIdx.x;
    int lane = tid & 31;
    int warp = tid >> 5;
    int wm   = warp >> 1;
    int wn   = warp & 1;
    int bm   = blockIdx.x * 128;
    int head = blockIdx.y;

    const __half* Ag = U + (size_t)bm * 1024 + head * 256;
    const __half* Bg = wd2T + (size_t)(head * 64) * 256;

    float acc[2][4][4];
    #pragma unroll
    for (int i = 0; i < 2; i++)
        #pragma unroll
        for (int j = 0; j < 4; j++)
            #pragma unroll
            for (int r = 0; r < 4; r++) acc[i][j][r] = 0.f;

    auto issue = [&](int kt, int buf) {
        __half* As = sp + buf * (192 * PE_ASTR);
        __half* Bs = As + 128 * PE_ASTR;
        #pragma unroll
        for (int q = 0; q < 2; q++) {
            int c  = tid * 2 + q;
            int ar = c >> 2, ak = (c & 3) * 8;
            uint32_t da = (uint32_t)__cvta_generic_to_shared(As + ar*PE_ASTR + ak);
            const __half* ga = Ag + (size_t)ar * 1024 + kt * 32 + ak;
            asm volatile("cp.async.cg.shared.global [%0], [%1], 16;\n"
                         :: "r"(da), "l"(ga));
        }
        {
            int br = tid >> 2, bk = (tid & 3) * 8;
            uint32_t db = (uint32_t)__cvta_generic_to_shared(Bs + br*PE_ASTR + bk);
            const __half* gb = Bg + (size_t)br * 256 + kt * 32 + bk;
            asm volatile("cp.async.cg.shared.global [%0], [%1], 16;\n"
                         :: "r"(db), "l"(gb));
        }
        asm volatile("cp.async.commit_group;\n");
    };

    const int nt = 8;
    issue(0, 0);
    issue(1, 1);
    asm volatile("cp.async.wait_group 1;\n");
    __syncthreads();

    for (int kt = 0; kt < nt; kt++) {
        int cur = kt % 3;
        bool more = (kt + 2) < nt;
        if (more) issue(kt + 2, (kt + 2) % 3);

        __half* As = sp + cur * (192 * PE_ASTR);
        __half* Bs = As + 128 * PE_ASTR;

        #pragma unroll
        for (int kk = 0; kk < 32; kk += 16) {
            uint32_t af[2][4], bf[2][4];
            #pragma unroll
            for (int i = 0; i < 2; i++) {
                int row = wm * 32 + i * 16 + (lane & 15);
                int kc  = kk + (lane >> 4) * 8;
                uint32_t ad = (uint32_t)__cvta_generic_to_shared(As + row*PE_ASTR + kc);
                asm volatile(
                    "ldmatrix.sync.aligned.m8n8.x4.shared.b16 {%0,%1,%2,%3}, [%4];"
                    : "=r"(af[i][0]), "=r"(af[i][1]), "=r"(af[i][2]), "=r"(af[i][3])
                    : "r"(ad));
            }
            #pragma unroll
            for (int j = 0; j < 2; j++) {
                int nrow = wn * 32 + j * 16 + (lane & 15);
                int kc   = kk + (lane >> 4) * 8;
                uint32_t bd = (uint32_t)__cvta_generic_to_shared(Bs + nrow*PE_ASTR + kc);
                asm volatile(
                    "ldmatrix.sync.aligned.m8n8.x4.shared.b16 {%0,%1,%2,%3}, [%4];"
                    : "=r"(bf[j][0]), "=r"(bf[j][1]), "=r"(bf[j][2]), "=r"(bf[j][3])
                    : "r"(bd));
            }
            #pragma unroll
            for (int j = 0; j < 2; j++)
                #pragma unroll
                for (int i = 0; i < 2; i++) {
                    mma16816(acc[i][2*j],     af[i], bf[j][0], bf[j][2]);
                    mma16816(acc[i][2*j + 1], af[i], bf[j][1], bf[j][3]);
                }
        }

        if (more) asm volatile("cp.async.wait_group 1;\n");
        else      asm volatile("cp.async.wait_group 0;\n");
        __syncthreads();
    }

    #pragma unroll
    for (int i = 0; i < 2; i++) {
        int row = bm + wm * 32 + i * 16 + (lane >> 2);
        #pragma unroll
        for (int jj = 0; jj < 4; jj++) {
            int col = head * 64 + wn * 32 + (jj >> 1) * 16 + (jj & 1) * 8 + (lane & 3) * 2;
            float2 a0 = __half22float2(*(const __half2*)&av[(size_t)row * CH + col]);
            float2 a1 = __half22float2(*(const __half2*)&av[(size_t)(row + 8) * CH + col]);
            *(__half2*)&s[(size_t)row * CH + col] =
                __floats2half2_rn(a0.x + acc[i][jj][0], a0.y + acc[i][jj][1]);
            *(__half2*)&s[(size_t)(row + 8) * CH + col] =
                __floats2half2_rn(a1.x + acc[i][jj][2], a1.y + acc[i][jj][3]);
        }
    }
}

// -------- KNN attention: warp/point, half2 datapath -----------------------
__global__ void __launch_bounds__(256, 3)
attn_kernel(const __half* __restrict__ qkv, const int* __restrict__ nns,
            const float* __restrict__ xyz,
            const float* __restrict__ w_d1, const float* __restrict__ b_d1,
            __half* __restrict__ avb, __half* __restrict__ ub)
{
    int lane = threadIdx.x & 31;
    int p    = threadIdx.x >> 5;
    int pi   = blockIdx.x * 8 + p;
    int bb   = pi >> 13;

    int nbr = 0; float rx = 0.f, ry = 0.f;
    if (lane < 16) {
        int j = nns[pi*32 + lane];
        nbr = (bb << 13) + j;
        rx = xyz[pi*2]     - xyz[nbr*2];
        ry = xyz[pi*2 + 1] - xyz[nbr*2 + 1];
    }

    __half2 qf2[4];
    {
        uint4 qv = *(const uint4*)(qkv + (size_t)pi*QKVW + lane*8);
        const __half2* qh = (const __half2*)&qv;
        #pragma unroll
        for (int i = 0; i < 4; i++) qf2[i] = qh[i];
    }

    float attn[16];
    #pragma unroll
    for (int k = 0; k < 16; k++) {
        int rowk = __shfl_sync(0xffffffffu, nbr, k);
        uint4 kv = *(const uint4*)(qkv + (size_t)rowk*QKVW + CH + lane*8);
        const __half2* kh = (const __half2*)&kv;
        __half2 acc2 = __floats2half2_rn(0.f, 0.f);
        #pragma unroll
        for (int i = 0; i < 4; i++) acc2 = __hfma2(qf2[i], kh[i], acc2);
        float2 pf = __half22float2(acc2);
        float pr = pf.x + pf.y;
        pr += __shfl_xor_sync(0xffffffffu, pr, 4);
        pr += __shfl_xor_sync(0xffffffffu, pr, 2);
        pr += __shfl_xor_sync(0xffffffffu, pr, 1);
        attn[k] = pr * 0.125f;
    }

    float mx = -1e30f;
    #pragma unroll
    for (int k = 0; k < 16; k++) mx = fmaxf(mx, attn[k]);
    float sm = 0.f;
    #pragma unroll
    for (int k = 0; k < 16; k++) { attn[k] = __expf(attn[k] - mx); sm += attn[k]; }
    float inv = 1.f / sm;
    #pragma unroll
    for (int k = 0; k < 16; k++) attn[k] *= inv;

    __half2 wx2[4], wy2[4], wb2[4];
    #pragma unroll
    for (int i = 0; i < 4; i++) {
        int c = lane*8 + 2*i;
        wx2[i] = __floats2half2_rn(w_d1[c],      w_d1[c+1]);
        wy2[i] = __floats2half2_rn(w_d1[CH+c],   w_d1[CH+c+1]);
        wb2[i] = __floats2half2_rn(b_d1[c],      b_d1[c+1]);
    }

    const __half2 z2 = __floats2half2_rn(0.f, 0.f);
    float av[8];
    __half2 u2[4][4];
    #pragma unroll
    for (int i = 0; i < 4; i++) {
        av[2*i] = av[2*i+1] = 0.f;
        u2[0][i] = u2[1][i] = u2[2][i] = u2[3][i] = z2;
    }

    #pragma unroll
    for (int k = 0; k < 16; k++) {
        int   rowk = __shfl_sync(0xffffffffu, nbr, k);
        float rxk  = __shfl_sync(0xffffffffu, rx, k);
        float ryk  = __shfl_sync(0xffffffffu, ry, k);
        float ak   = attn[k];
        __half2 a02 = __float2half2_rn(__shfl_sync(0xffffffffu, attn[k], 0));
        __half2 a12 = __float2half2_rn(__shfl_sync(0xffffffffu, attn[k], 8));
        __half2 a22 = __float2half2_rn(__shfl_sync(0xffffffffu, attn[k], 16));
        __half2 a32 = __float2half2_rn(__shfl_sync(0xffffffffu, attn[k], 24));
        __half2 rx2 = __float2half2_rn(rxk);
        __half2 ry2 = __float2half2_rn(ryk);

        uint4 vv = *(const uint4*)(qkv + (size_t)rowk*QKVW + 2*CH + lane*8);
        const __half2* vh = (const __half2*)&vv;
        #pragma unroll
        for (int i = 0; i < 4; i++) {
            __half2 t2 = __hmax2(__hfma2(rx2, wx2[i],
                                 __hfma2(ry2, wy2[i], wb2[i])), z2);
            u2[0][i] = __hfma2(a02, t2, u2[0][i]);
            u2[1][i] = __hfma2(a12, t2, u2[1][i]);
            u2[2][i] = __hfma2(a22, t2, u2[2][i]);
            u2[3][i] = __hfma2(a32, t2, u2[3][i]);
            float2 vf = __half22float2(vh[i]);
            av[2*i]   = fmaf(ak, vf.x, av[2*i]);
            av[2*i+1] = fmaf(ak, vf.y, av[2*i+1]);
        }
    }

    {
        __half2 t4[4];
        #pragma unroll
        for (int i = 0; i < 4; i++)
            t4[i] = __floats2half2_rn(av[2*i], av[2*i+1]);
        *(uint4*)(avb + (size_t)pi*CH + lane*8) = *(uint4*)t4;
    }
    #pragma unroll
    for (int h = 0; h < 4; h++)
        *(uint4*)(ub + (size_t)pi*1024 + h*256 + lane*8) = *(uint4*)(u2[h]);
}

// -------------------- launch ----------------------------------------------
extern "C" void kernel_launch(void* const* d_in, const int* in_sizes, int n_in,
                              void* d_out, int out_size)
{
    const float* xyz      = (const float*)d_in[0];
    const float* xy_embed = (const float*)d_in[1];
    const int*   nns      = (const int*)  d_in[2];
    const float* ln1_g    = (const float*)d_in[3];
    const float* ln1_b    = (const float*)d_in[4];
    const float* w_qkv    = (const float*)d_in[5];
    const float* w_d1     = (const float*)d_in[6];
    const float* b_d1     = (const float*)d_in[7];
    const float* w_d2     = (const float*)d_in[8];
    const float* b_d2     = (const float*)d_in[9];
    const float* w_proj   = (const float*)d_in[10];
    const float* b_proj   = (const float*)d_in[11];
    const float* ln2_g    = (const float*)d_in[12];
    const float* ln2_b    = (const float*)d_in[13];
    const float* w_m1     = (const float*)d_in[14];
    const float* b_m1     = (const float*)d_in[15];
    const float* w_m2     = (const float*)d_in[16];
    const float* b_m2     = (const float*)d_in[17];
    float* out = (float*)d_out;

    __half *h, *qkvh, *avb, *ub, *s16, *mlp1, *wqkvT, *wm1T, *wm2T, *wprojT, *wd2T;
    float *x, *bfold;
    cudaGetSymbolAddress((void**)&h,      g_h);
    cudaGetSymbolAddress((void**)&qkvh,   g_qkvh);
    cudaGetSymbolAddress((void**)&avb,    g_av);
    cudaGetSymbolAddress((void**)&ub,     g_u);
    cudaGetSymbolAddress((void**)&s16,    g_s);
    cudaGetSymbolAddress((void**)&x,      g_x);
    cudaGetSymbolAddress((void**)&mlp1,   g_mlp1);
    cudaGetSymbolAddress((void**)&wqkvT,  g_wqkvT);
    cudaGetSymbolAddress((void**)&wm1T,   g_wm1T);
    cudaGetSymbolAddress((void**)&wm2T,   g_wm2T);
    cudaGetSymbolAddress((void**)&wprojT, g_wprojT);
    cudaGetSymbolAddress((void**)&wd2T,   g_wd2T);
    cudaGetSymbolAddress((void**)&bfold,  g_bfold);

    cudaFuncSetAttribute(hgemm<0, __half>,
        cudaFuncAttributeMaxDynamicSharedMemorySize, HSMEM_BYTES);
    cudaFuncSetAttribute(hgemm<1, float>,
        cudaFuncAttributeMaxDynamicSharedMemorySize, HSMEM_BYTES);
    cudaFuncSetAttribute(hgemm<2, __half>,
        cudaFuncAttributeMaxDynamicSharedMemorySize, HSMEM_BYTES);

    // 0. prologue: tiled transposes + bfold (one launch)
    prologue_all<<<dim3(32, 32, 6), dim3(32, 8)>>>(
        w_qkv, w_m1, w_m2, w_proj, w_d2, b_d2, b_proj,
        wqkvT, wm1T, wm2T, wprojT, wd2T, bfold);

    // 1. LN1 -> half
    ln_kernel<<<NPTS/8, 256>>>(xy_embed, ln1_g, ln1_b, h);
    // 2. qkv = h @ w_qkv  (N=768, K=256)  — persistent grid
    hgemm<0, __half><<<PGRID, 256, HSMEM_BYTES>>>(
        h, wqkvT, qkvh, NPTS, QKVW, CH, nullptr, nullptr);
    // 3. KNN attention -> av, U
    attn_kernel<<<NPTS/8, 256>>>(qkvh, nns, xyz, w_d1, b_d1, avb, ub);
    // 3.5 pe: s = av + U_h @ w_d2[:, h-slice]
    pe_gemm<<<dim3(NPTS/128, 4), 256>>>(ub, wd2T, avb, s16);
    // 4. x = xy_embed + s @ w_proj + bfold  (N=256, K=256)
    hgemm<1, float><<<PGRID, 256, HSMEM_BYTES>>>(
        s16, wprojT, x, NPTS, CH, CH, bfold, xy_embed);
    // 5. LN2 -> half
    ln_kernel<<<NPTS/8, 256>>>(x, ln2_g, ln2_b, h);
    // 6. mlp1 = gelu(h @ w_m1 + b_m1)  (N=1024, K=256)
    hgemm<2, __half><<<PGRID, 256, HSMEM_BYTES>>>(
        h, wm1T, mlp1, NPTS, 1024, CH, b_m1, nullptr);
    // 7. out = x + mlp1 @ w_m2 + b_m2  (N=256, K=1024)
    hgemm<1, float><<<PGRID, 256, HSMEM_BYTES>>>(
        mlp1, wm2T, out, NPTS, CH, 1024, b_m2, x);
}

// round 16
// speedup vs baseline: 1.0439x; 1.0439x over previous
#include <cuda_runtime.h>
#include <cuda_fp16.h>
#include <math.h>
#include <stdint.h>

#define BSZ   4
#define NPT   8192
#define CH    256
#define NPTS  (BSZ*NPT)      // 32768
#define QKVW  768

// -------------------- scratch (device globals; no cudaMalloc allowed) -----
__device__ __half g_h[NPTS*CH];          // LN out
__device__ __half g_qkvh[NPTS*QKVW];
__device__ __half g_av[NPTS*CH];         // attn-weighted V
__device__ __half g_u[NPTS*1024];        // pe basis U: [p][h][256]
__device__ __half g_s[NPTS*CH];          // av + pe (proj GEMM input)
__device__ float  g_x[NPTS*CH];          // residual stream
__device__ __half g_mlp1[NPTS*1024];
__device__ __half g_wqkvT[QKVW*CH];      // [768][256]   Bt (N,K)
__device__ __half g_wm1T[1024*CH];       // [1024][256]
__device__ __half g_wm2T[CH*1024];       // [256][1024]
__device__ __half g_wprojT[CH*CH];       // [256][256]
__device__ __half g_wd2T[CH*CH];         // wd2T[n][k] = w_d2[k][n]
__device__ float  g_bfold[CH];           // b_proj + b_d2 @ w_proj

// ==================== prologue: tiled transposes + bfold ==================
__global__ void prologue_all(const float* __restrict__ w_qkv,
                             const float* __restrict__ w_m1,
                             const float* __restrict__ w_m2,
                             const float* __restrict__ w_proj,
                             const float* __restrict__ w_d2,
                             const float* __restrict__ b_d2,
                             const float* __restrict__ b_proj,
                             __half* __restrict__ qkvT, __half* __restrict__ m1T,
                             __half* __restrict__ m2T,  __half* __restrict__ projT,
                             __half* __restrict__ d2T,  float* __restrict__ bfold)
{
    int z = blockIdx.z;
    if (z == 5) {
        if (blockIdx.x || blockIdx.y) return;
        int c = threadIdx.y * 32 + threadIdx.x;   // 0..255
        float acc = b_proj[c];
        #pragma unroll 8
        for (int cc = 0; cc < CH; cc++)
            acc = fmaf(b_d2[cc], w_proj[cc*CH + c], acc);
        bfold[c] = acc;
        return;
    }
    const float* src; __half* dst; int R, C;
    switch (z) {
        case 0: src = w_qkv;  dst = qkvT;  R = 256;  C = 768;  break;
        case 1: src = w_m1;   dst = m1T;   R = 256;  C = 1024; break;
        case 2: src = w_m2;   dst = m2T;   R = 1024; C = 256;  break;
        case 3: src = w_proj; dst = projT; R = 256;  C = 256;  break;
        default:src = w_d2;   dst = d2T;   R = 256;  C = 256;  break;
    }
    int bx = blockIdx.x * 32, by = blockIdx.y * 32;
    if (bx >= C || by >= R) return;
    __shared__ float t[32][33];
    #pragma unroll
    for (int j = 0; j < 32; j += 8)
        t[threadIdx.y + j][threadIdx.x] =
            src[(size_t)(by + threadIdx.y + j) * C + bx + threadIdx.x];
    __syncthreads();
    #pragma unroll
    for (int j = 0; j < 32; j += 8)
        dst[(size_t)(bx + threadIdx.y + j) * R + by + threadIdx.x] =
            __float2half(t[threadIdx.x][threadIdx.y + j]);
}

// -------------------- LayerNorm (warp per row) ----------------------------
__global__ void __launch_bounds__(256)
ln_kernel(const float* __restrict__ x, const float* __restrict__ g,
          const float* __restrict__ b, __half* __restrict__ out)
{
    int warp = threadIdx.x >> 5, lane = threadIdx.x & 31;
    int row  = blockIdx.x * 8 + warp;
    const float* xr = x + (size_t)row*CH + lane*8;

    float v[8];
    *(float4*)(v)     = *(const float4*)(xr);
    *(float4*)(v + 4) = *(const float4*)(xr + 4);

    float s = 0.f;
    #pragma unroll
    for (int j = 0; j < 8; j++) s += v[j];
    #pragma unroll
    for (int o = 16; o > 0; o >>= 1) s += __shfl_xor_sync(0xffffffffu, s, o);
    float mean = s * (1.0f / CH);

    float d[8], ss = 0.f;
    #pragma unroll
    for (int j = 0; j < 8; j++) { d[j] = v[j] - mean; ss += d[j]*d[j]; }
    #pragma unroll
    for (int o = 16; o > 0; o >>= 1) ss += __shfl_xor_sync(0xffffffffu, ss, o);
    float rstd = rsqrtf(ss * (1.0f / CH) + 1e-5f);

    float gv[8], bv[8];
    *(float4*)(gv)     = *(const float4*)(g + lane*8);
    *(float4*)(gv + 4) = *(const float4*)(g + lane*8 + 4);
    *(float4*)(bv)     = *(const float4*)(b + lane*8);
    *(float4*)(bv + 4) = *(const float4*)(b + lane*8 + 4);

    __half2 o2[4];
    #pragma unroll
    for (int j = 0; j < 4; j++)
        o2[j] = __floats2half2_rn(d[2*j]*rstd*gv[2*j] + bv[2*j],
                                  d[2*j+1]*rstd*gv[2*j+1] + bv[2*j+1]);
    *(uint4*)(out + (size_t)row*CH + lane*8) = *(uint4*)o2;
}

// ----- fp16 tensor-core GEMM (128x128x64, 3-stage, XOR-swizzled smem) -----
// Rows are exactly 128 B; 16-B chunk c of row r lives at chunk (c ^ (r&7)).
// ldmatrix lane addresses then hit banks 4*(c^(r&7)) — distinct over 8 rows.
__device__ __forceinline__ float gelu_exact(float v) { return v * normcdff(v); }

#define HBM 128
#define HBN 128
#define HBK 64
#define A_HALVES (HBM*HBK)            // 8192 halves = 16 KB
#define STAGE_H  (2*A_HALVES)         // A + B
#define HSMEM_BYTES (3*STAGE_H*2)     // 98304 B (3 stages)

__device__ __forceinline__ void mma16816(float* c, const uint32_t* a,
                                         uint32_t b0, uint32_t b1)
{
    asm volatile(
        "mma.sync.aligned.m16n8k16.row.col.f32.f16.f16.f32 "
        "{%0,%1,%2,%3}, {%4,%5,%6,%7}, {%8,%9}, {%0,%1,%2,%3};"
        : "+f"(c[0]), "+f"(c[1]), "+f"(c[2]), "+f"(c[3])
        : "r"(a[0]), "r"(a[1]), "r"(a[2]), "r"(a[3]), "r"(b0), "r"(b1));
}

template<int EPI, typename OutT>
__global__ void __launch_bounds__(256, 2)
hgemm(const __half* __restrict__ A, const __half* __restrict__ B,
      OutT* __restrict__ C, int M, int N, int K,
      const float* __restrict__ bias, const float* __restrict__ resid)
{
    extern __shared__ __half sh[];

    int tid  = threadIdx.x;
    int lane = tid & 31;
    int warp = tid >> 5;
    int wm   = warp & 1;
    int wn   = warp >> 1;
    int bm   = blockIdx.y * HBM;
    int bn   = blockIdx.x * HBN;

    const __half* Ag = A + (size_t)bm * K;
    const __half* Bg = B + (size_t)bn * K;      // Bt layout [N][K]

    float acc[4][4][4];
    #pragma unroll
    for (int i = 0; i < 4; i++)
        #pragma unroll
        for (int j = 0; j < 4; j++)
            #pragma unroll
            for (int r = 0; r < 4; r++) acc[i][j][r] = 0.f;

    auto issue = [&](int kt, int buf) {
        __half* As = sh + buf * STAGE_H;
        __half* Bs = As + A_HALVES;
        #pragma unroll
        for (int s = 0; s < 4; s++) {
            int c  = tid * 4 + s;               // 0..1023
            int r  = c >> 3, ch = c & 7;
            int sw = ch ^ (r & 7);
            uint32_t da = (uint32_t)__cvta_generic_to_shared(As + r*64 + sw*8);
            const __half* ga = Ag + (size_t)r * K + kt * HBK + ch*8;
            asm volatile("cp.async.cg.shared.global [%0], [%1], 16;\n"
                         :: "r"(da), "l"(ga));
            uint32_t db = (uint32_t)__cvta_generic_to_shared(Bs + r*64 + sw*8);
            const __half* gb = Bg + (size_t)r * K + kt * HBK + ch*8;
            asm volatile("cp.async.cg.shared.global [%0], [%1], 16;\n"
                         :: "r"(db), "l"(gb));
        }
        asm volatile("cp.async.commit_group;\n");
    };

    int nt = K / HBK;                 // 4 (K=256) or 16 (K=1024)
    issue(0, 0);
    issue(1, 1);
    asm volatile("cp.async.wait_group 1;\n");
    __syncthreads();

    for (int kt = 0; kt < nt; kt++) {
        int cur = kt % 3;
        bool more = (kt + 2) < nt;
        if (more) issue(kt + 2, (kt + 2) % 3);

        __half* As = sh + cur * STAGE_H;
        __half* Bs = As + A_HALVES;

        #pragma unroll
        for (int kk = 0; kk < HBK; kk += 16) {
            uint32_t af[4][4];
            #pragma unroll
            for (int i = 0; i < 4; i++) {
                int row   = wm * 64 + i * 16 + (lane & 15);
                int chunk = (kk >> 3) + (lane >> 4);
                uint32_t ad = (uint32_t)__cvta_generic_to_shared(
                    As + row*64 + ((chunk ^ (row & 7)) * 8));
                asm volatile(
                    "ldmatrix.sync.aligned.m8n8.x4.shared.b16 {%0,%1,%2,%3}, [%4];"
                    : "=r"(af[i][0]), "=r"(af[i][1]), "=r"(af[i][2]), "=r"(af[i][3])
                    : "r"(ad));
            }
            #pragma unroll
            for (int j = 0; j < 2; j++) {
                uint32_t bf[4];
                int nrow  = wn * 32 + j * 16 + (lane & 15);
                int chunk = (kk >> 3) + (lane >> 4);
                uint32_t bd = (uint32_t)__cvta_generic_to_shared(
                    Bs + nrow*64 + ((chunk ^ (nrow & 7)) * 8));
                asm volatile(
                    "ldmatrix.sync.aligned.m8n8.x4.shared.b16 {%0,%1,%2,%3}, [%4];"
                    : "=r"(bf[0]), "=r"(bf[1]), "=r"(bf[2]), "=r"(bf[3])
                    : "r"(bd));
                #pragma unroll
                for (int i = 0; i < 4; i++) {
                    mma16816(acc[i][2*j],     af[i], bf[0], bf[2]);
                    mma16816(acc[i][2*j + 1], af[i], bf[1], bf[3]);
                }
            }
        }

        if (more) asm volatile("cp.async.wait_group 1;\n");
        else      asm volatile("cp.async.wait_group 0;\n");
        __syncthreads();
    }

    #pragma unroll
    for (int i = 0; i < 4; i++) {
        int row = bm + wm * 64 + i * 16 + (lane >> 2);
        #pragma unroll
        for (int jj = 0; jj < 4; jj++) {
            int col = bn + wn * 32 + (jj >> 1) * 16 + (jj & 1) * 8 + (lane & 3) * 2;
            float2 v0 = make_float2(acc[i][jj][0], acc[i][jj][1]);
            float2 v1 = make_float2(acc[i][jj][2], acc[i][jj][3]);
            if (EPI >= 1) {
                float2 bv = *(const float2*)&bias[col];
                v0.x += bv.x; v0.y += bv.y;
                v1.x += bv.x; v1.y += bv.y;
            }
            if (EPI == 1) {
                float2 r0 = *(const float2*)&resid[(size_t)row * N + col];
                float2 r1 = *(const float2*)&resid[(size_t)(row + 8) * N + col];
                v0.x += r0.x; v0.y += r0.y;
                v1.x += r1.x; v1.y += r1.y;
            }
            if (EPI == 2) {
                v0.x = gelu_exact(v0.x); v0.y = gelu_exact(v0.y);
                v1.x = gelu_exact(v1.x); v1.y = gelu_exact(v1.y);
            }
            if constexpr (sizeof(OutT) == 2) {
                *(__half2*)&C[(size_t)row * N + col]       = __floats2half2_rn(v0.x, v0.y);
                *(__half2*)&C[(size_t)(row + 8) * N + col] = __floats2half2_rn(v1.x, v1.y);
            } else {
                *(float2*)&C[(size_t)row * N + col]       = v0;
                *(float2*)&C[(size_t)(row + 8) * N + col] = v1;
            }
        }
    }
}

// ==================== pe GEMM: s = av + U_h @ w_d2[:, h-slice] ============
#define PE_ASTR 40
__global__ void __launch_bounds__(256, 2)
pe_gemm(const __half* __restrict__ U, const __half* __restrict__ wd2T,
        const __half* __restrict__ av, __half* __restrict__ s)
{
    __shared__ __half sp[3 * 192 * PE_ASTR];

    int tid  = threadIdx.x;
    int lane = tid & 31;
    int warp = tid >> 5;
    int wm   = warp >> 1;
    int wn   = warp & 1;
    int bm   = blockIdx.x * 128;
    int head = blockIdx.y;

    const __half* Ag = U + (size_t)bm * 1024 + head * 256;
    const __half* Bg = wd2T + (size_t)(head * 64) * 256;

    float acc[2][4][4];
    #pragma unroll
    for (int i = 0; i < 2; i++)
        #pragma unroll
        for (int j = 0; j < 4; j++)
            #pragma unroll
            for (int r = 0; r < 4; r++) acc[i][j][r] = 0.f;

    auto issue = [&](int kt, int buf) {
        __half* As = sp + buf * (192 * PE_ASTR);
        __half* Bs = As + 128 * PE_ASTR;
        #pragma unroll
        for (int q = 0; q < 2; q++) {
            int c  = tid * 2 + q;
            int ar = c >> 2, ak = (c & 3) * 8;
            uint32_t da = (uint32_t)__cvta_generic_to_shared(As + ar*PE_ASTR + ak);
            const __half* ga = Ag + (size_t)ar * 1024 + kt * 32 + ak;
            asm volatile("cp.async.cg.shared.global [%0], [%1], 16;\n"
                         :: "r"(da), "l"(ga));
        }
        {
            int br = tid >> 2, bk = (tid & 3) * 8;
            uint32_t db = (uint32_t)__cvta_generic_to_shared(Bs + br*PE_ASTR + bk);
            const __half* gb = Bg + (size_t)br * 256 + kt * 32 + bk;
            asm volatile("cp.async.cg.shared.global [%0], [%1], 16;\n"
                         :: "r"(db), "l"(gb));
        }
        asm volatile("cp.async.commit_group;\n");
    };

    const int nt = 8;
    issue(0, 0);
    issue(1, 1);
    asm volatile("cp.async.wait_group 1;\n");
    __syncthreads();

    for (int kt = 0; kt < nt; kt++) {
        int cur = kt % 3;
        bool more = (kt + 2) < nt;
        if (more) issue(kt + 2, (kt + 2) % 3);

        __half* As = sp + cur * (192 * PE_ASTR);
        __half* Bs = As + 128 * PE_ASTR;

        #pragma unroll
        for (int kk = 0; kk < 32; kk += 16) {
            uint32_t af[2][4];
            #pragma unroll
            for (int i = 0; i < 2; i++) {
                int row = wm * 32 + i * 16 + (lane & 15);
                int kc  = kk + (lane >> 4) * 8;
                uint32_t ad = (uint32_t)__cvta_generic_to_shared(As + row*PE_ASTR + kc);
                asm volatile(
                    "ldmatrix.sync.aligned.m8n8.x4.shared.b16 {%0,%1,%2,%3}, [%4];"
                    : "=r"(af[i][0]), "=r"(af[i][1]), "=r"(af[i][2]), "=r"(af[i][3])
                    : "r"(ad));
            }
            #pragma unroll
            for (int j = 0; j < 2; j++) {
                uint32_t bf[4];
                int nrow = wn * 32 + j * 16 + (lane & 15);
                int kc   = kk + (lane >> 4) * 8;
                uint32_t bd = (uint32_t)__cvta_generic_to_shared(Bs + nrow*PE_ASTR + kc);
                asm volatile(
                    "ldmatrix.sync.aligned.m8n8.x4.shared.b16 {%0,%1,%2,%3}, [%4];"
                    : "=r"(bf[0]), "=r"(bf[1]), "=r"(bf[2]), "=r"(bf[3])
                    : "r"(bd));
                #pragma unroll
                for (int i = 0; i < 2; i++) {
                    mma16816(acc[i][2*j],     af[i], bf[0], bf[2]);
                    mma16816(acc[i][2*j + 1], af[i], bf[1], bf[3]);
                }
            }
        }

        if (more) asm volatile("cp.async.wait_group 1;\n");
        else      asm volatile("cp.async.wait_group 0;\n");
        __syncthreads();
    }

    #pragma unroll
    for (int i = 0; i < 2; i++) {
        int row = bm + wm * 32 + i * 16 + (lane >> 2);
        #pragma unroll
        for (int jj = 0; jj < 4; jj++) {
            int col = head * 64 + wn * 32 + (jj >> 1) * 16 + (jj & 1) * 8 + (lane & 3) * 2;
            float2 a0 = __half22float2(*(const __half2*)&av[(size_t)row * CH + col]);
            float2 a1 = __half22float2(*(const __half2*)&av[(size_t)(row + 8) * CH + col]);
            *(__half2*)&s[(size_t)row * CH + col] =
                __floats2half2_rn(a0.x + acc[i][jj][0], a0.y + acc[i][jj][1]);
            *(__half2*)&s[(size_t)(row + 8) * CH + col] =
                __floats2half2_rn(a1.x + acc[i][jj][2], a1.y + acc[i][jj][3]);
        }
    }
}

// -------- KNN attention: warp/point, half2 datapath (R12 best) ------------
__global__ void __launch_bounds__(256, 3)
attn_kernel(const __half* __restrict__ qkv, const int* __restrict__ nns,
            const float* __restrict__ xyz,
            const float* __restrict__ w_d1, const float* __restrict__ b_d1,
            __half* __restrict__ avb, __half* __restrict__ ub)
{
    int lane = threadIdx.x & 31;
    int p    = threadIdx.x >> 5;
    int pi   = blockIdx.x * 8 + p;
    int bb   = pi >> 13;

    int nbr = 0; float rx = 0.f, ry = 0.f;
    if (lane < 16) {
        int j = nns[pi*32 + lane];
        nbr = (bb << 13) + j;
        rx = xyz[pi*2]     - xyz[nbr*2];
        ry = xyz[pi*2 + 1] - xyz[nbr*2 + 1];
    }

    __half2 qf2[4];
    {
        uint4 qv = *(const uint4*)(qkv + (size_t)pi*QKVW + lane*8);
        const __half2* qh = (const __half2*)&qv;
        #pragma unroll
        for (int i = 0; i < 4; i++) qf2[i] = qh[i];
    }

    float attn[16];
    #pragma unroll
    for (int k = 0; k < 16; k++) {
        int rowk = __shfl_sync(0xffffffffu, nbr, k);
        uint4 kv = *(const uint4*)(qkv + (size_t)rowk*QKVW + CH + lane*8);
        const __half2* kh = (const __half2*)&kv;
        __half2 acc2 = __floats2half2_rn(0.f, 0.f);
        #pragma unroll
        for (int i = 0; i < 4; i++) acc2 = __hfma2(qf2[i], kh[i], acc2);
        float2 pf = __half22float2(acc2);
        float pr = pf.x + pf.y;
        pr += __shfl_xor_sync(0xffffffffu, pr, 4);
        pr += __shfl_xor_sync(0xffffffffu, pr, 2);
        pr += __shfl_xor_sync(0xffffffffu, pr, 1);
        attn[k] = pr * 0.125f;
    }

    float mx = -1e30f;
    #pragma unroll
    for (int k = 0; k < 16; k++) mx = fmaxf(mx, attn[k]);
    float sm = 0.f;
    #pragma unroll
    for (int k = 0; k < 16; k++) { attn[k] = __expf(attn[k] - mx); sm += attn[k]; }
    float inv = 1.f / sm;
    #pragma unroll
    for (int k = 0; k < 16; k++) attn[k] *= inv;

    __half2 wx2[4], wy2[4], wb2[4];
    #pragma unroll
    for (int i = 0; i < 4; i++) {
        int c = lane*8 + 2*i;
        wx2[i] = __floats2half2_rn(w_d1[c],      w_d1[c+1]);
        wy2[i] = __floats2half2_rn(w_d1[CH+c],   w_d1[CH+c+1]);
        wb2[i] = __floats2half2_rn(b_d1[c],      b_d1[c+1]);
    }

    const __half2 z2 = __floats2half2_rn(0.f, 0.f);
    float av[8];
    __half2 u2[4][4];
    #pragma unroll
    for (int i = 0; i < 4; i++) {
        av[2*i] = av[2*i+1] = 0.f;
        u2[0][i] = u2[1][i] = u2[2][i] = u2[3][i] = z2;
    }

    #pragma unroll
    for (int k = 0; k < 16; k++) {
        int   rowk = __shfl_sync(0xffffffffu, nbr, k);
        float rxk  = __shfl_sync(0xffffffffu, rx, k);
        float ryk  = __shfl_sync(0xffffffffu, ry, k);
        float ak   = attn[k];
        __half2 a02 = __float2half2_rn(__shfl_sync(0xffffffffu, attn[k], 0));
        __half2 a12 = __float2half2_rn(__shfl_sync(0xffffffffu, attn[k], 8));
        __half2 a22 = __float2half2_rn(__shfl_sync(0xffffffffu, attn[k], 16));
        __half2 a32 = __float2half2_rn(__shfl_sync(0xffffffffu, attn[k], 24));
        __half2 rx2 = __float2half2_rn(rxk);
        __half2 ry2 = __float2half2_rn(ryk);

        uint4 vv = *(const uint4*)(qkv + (size_t)rowk*QKVW + 2*CH + lane*8);
        const __half2* vh = (const __half2*)&vv;
        #pragma unroll
        for (int i = 0; i < 4; i++) {
            __half2 t2 = __hmax2(__hfma2(rx2, wx2[i],
                                 __hfma2(ry2, wy2[i], wb2[i])), z2);
            u2[0][i] = __hfma2(a02, t2, u2[0][i]);
            u2[1][i] = __hfma2(a12, t2, u2[1][i]);
            u2[2][i] = __hfma2(a22, t2, u2[2][i]);
            u2[3][i] = __hfma2(a32, t2, u2[3][i]);
            float2 vf = __half22float2(vh[i]);
            av[2*i]   = fmaf(ak, vf.x, av[2*i]);
            av[2*i+1] = fmaf(ak, vf.y, av[2*i+1]);
        }
    }

    {
        __half2 t4[4];
        #pragma unroll
        for (int i = 0; i < 4; i++)
            t4[i] = __floats2half2_rn(av[2*i], av[2*i+1]);
        *(uint4*)(avb + (size_t)pi*CH + lane*8) = *(uint4*)t4;
    }
    #pragma unroll
    for (int h = 0; h < 4; h++)
        *(uint4*)(ub + (size_t)pi*1024 + h*256 + lane*8) = *(uint4*)(u2[h]);
}

// -------------------- launch ----------------------------------------------
extern "C" void kernel_launch(void* const* d_in, const int* in_sizes, int n_in,
                              void* d_out, int out_size)
{
    const float* xyz      = (const float*)d_in[0];
    const float* xy_embed = (const float*)d_in[1];
    const int*   nns      = (const int*)  d_in[2];
    const float* ln1_g    = (const float*)d_in[3];
    const float* ln1_b    = (const float*)d_in[4];
    const float* w_qkv    = (const float*)d_in[5];
    const float* w_d1     = (const float*)d_in[6];
    const float* b_d1     = (const float*)d_in[7];
    const float* w_d2     = (const float*)d_in[8];
    const float* b_d2     = (const float*)d_in[9];
    const float* w_proj   = (const float*)d_in[10];
    const float* b_proj   = (const float*)d_in[11];
    const float* ln2_g    = (const float*)d_in[12];
    const float* ln2_b    = (const float*)d_in[13];
    const float* w_m1     = (const float*)d_in[14];
    const float* b_m1     = (const float*)d_in[15];
    const float* w_m2     = (const float*)d_in[16];
    const float* b_m2     = (const float*)d_in[17];
    float* out = (float*)d_out;

    __half *h, *qkvh, *avb, *ub, *s16, *mlp1, *wqkvT, *wm1T, *wm2T, *wprojT, *wd2T;
    float *x, *bfold;
    cudaGetSymbolAddress((void**)&h,      g_h);
    cudaGetSymbolAddress((void**)&qkvh,   g_qkvh);
    cudaGetSymbolAddress((void**)&avb,    g_av);
    cudaGetSymbolAddress((void**)&ub,     g_u);
    cudaGetSymbolAddress((void**)&s16,    g_s);
    cudaGetSymbolAddress((void**)&x,      g_x);
    cudaGetSymbolAddress((void**)&mlp1,   g_mlp1);
    cudaGetSymbolAddress((void**)&wqkvT,  g_wqkvT);
    cudaGetSymbolAddress((void**)&wm1T,   g_wm1T);
    cudaGetSymbolAddress((void**)&wm2T,   g_wm2T);
    cudaGetSymbolAddress((void**)&wprojT, g_wprojT);
    cudaGetSymbolAddress((void**)&wd2T,   g_wd2T);
    cudaGetSymbolAddress((void**)&bfold,  g_bfold);

    cudaFuncSetAttribute(hgemm<0, __half>,
        cudaFuncAttributeMaxDynamicSharedMemorySize, HSMEM_BYTES);
    cudaFuncSetAttribute(hgemm<1, float>,
        cudaFuncAttributeMaxDynamicSharedMemorySize, HSMEM_BYTES);
    cudaFuncSetAttribute(hgemm<2, __half>,
        cudaFuncAttributeMaxDynamicSharedMemorySize, HSMEM_BYTES);

    // 0. prologue: tiled transposes + bfold (one launch)
    prologue_all<<<dim3(32, 32, 6), dim3(32, 8)>>>(
        w_qkv, w_m1, w_m2, w_proj, w_d2, b_d2, b_proj,
        wqkvT, wm1T, wm2T, wprojT, wd2T, bfold);

    // 1. LN1 -> half
    ln_kernel<<<NPTS/8, 256>>>(xy_embed, ln1_g, ln1_b, h);
    // 2. qkv = h @ w_qkv  (N=768, K=256)
    hgemm<0, __half><<<dim3(QKVW/HBN, NPTS/HBM), 256, HSMEM_BYTES>>>(
        h, wqkvT, qkvh, NPTS, QKVW, CH, nullptr, nullptr);
    // 3. KNN attention -> av, U
    attn_kernel<<<NPTS/8, 256>>>(qkvh, nns, xyz, w_d1, b_d1, avb, ub);
    // 3.5 pe: s = av + U_h @ w_d2[:, h-slice]
    pe_gemm<<<dim3(NPTS/128, 4), 256>>>(ub, wd2T, avb, s16);
    // 4. x = xy_embed + s @ w_proj + bfold  (N=256, K=256)
    hgemm<1, float><<<dim3(CH/HBN, NPTS/HBM), 256, HSMEM_BYTES>>>(
        s16, wprojT, x, NPTS, CH, CH, bfold, xy_embed);
    // 5. LN2 -> half
    ln_kernel<<<NPTS/8, 256>>>(x, ln2_g, ln2_b, h);
    // 6. mlp1 = gelu(h @ w_m1 + b_m1)  (N=1024, K=256)
    hgemm<2, __half><<<dim3(1024/HBN, NPTS/HBM), 256, HSMEM_BYTES>>>(
        h, wm1T, mlp1, NPTS, 1024, CH, b_m1, nullptr);
    // 7. out = x + mlp1 @ w_m2 + b_m2  (N=256, K=1024)
    hgemm<1, float><<<dim3(CH/HBN, NPTS/HBM), 256, HSMEM_BYTES>>>(
        mlp1, wm2T, out, NPTS, CH, 1024, b_m2, x);
}

// round 17
// speedup vs baseline: 1.0505x; 1.0063x over previous
#include <cuda_runtime.h>
#include <cuda_fp16.h>
#include <math.h>
#include <stdint.h>

#define BSZ   4
#define NPT   8192
#define CH    256
#define NPTS  (BSZ*NPT)      // 32768
#define QKVW  768

// -------------------- scratch (device globals; no cudaMalloc allowed) -----
__device__ __half g_h[NPTS*CH];          // LN out
__device__ __half g_qkvh[NPTS*QKVW];
__device__ __half g_av[NPTS*CH];         // attn-weighted V
__device__ __half g_u[NPTS*1024];        // pe basis U: [p][h][256]
__device__ __half g_s[NPTS*CH];          // av + pe (proj GEMM input)
__device__ float  g_x[NPTS*CH];          // residual stream
__device__ __half g_mlp1[NPTS*1024];
__device__ __half g_wqkvT[QKVW*CH];      // [768][256]   Bt (N,K)
__device__ __half g_wm1T[1024*CH];       // [1024][256]
__device__ __half g_wm2T[CH*1024];       // [256][1024]
__device__ __half g_wprojT[CH*CH];       // [256][256]
__device__ __half g_wd2T[CH*CH];         // wd2T[n][k] = w_d2[k][n]
__device__ float  g_bfold[CH];           // b_proj + b_d2 @ w_proj

// ==================== prologue: tiled transposes + bfold ==================
__global__ void prologue_all(const float* __restrict__ w_qkv,
                             const float* __restrict__ w_m1,
                             const float* __restrict__ w_m2,
                             const float* __restrict__ w_proj,
                             const float* __restrict__ w_d2,
                             const float* __restrict__ b_d2,
                             const float* __restrict__ b_proj,
                             __half* __restrict__ qkvT, __half* __restrict__ m1T,
                             __half* __restrict__ m2T,  __half* __restrict__ projT,
                             __half* __restrict__ d2T,  float* __restrict__ bfold)
{
    int z = blockIdx.z;
    if (z == 5) {
        if (blockIdx.x || blockIdx.y) return;
        int c = threadIdx.y * 32 + threadIdx.x;   // 0..255
        float acc = b_proj[c];
        #pragma unroll 8
        for (int cc = 0; cc < CH; cc++)
            acc = fmaf(b_d2[cc], w_proj[cc*CH + c], acc);
        bfold[c] = acc;
        return;
    }
    const float* src; __half* dst; int R, C;
    switch (z) {
        case 0: src = w_qkv;  dst = qkvT;  R = 256;  C = 768;  break;
        case 1: src = w_m1;   dst = m1T;   R = 256;  C = 1024; break;
        case 2: src = w_m2;   dst = m2T;   R = 1024; C = 256;  break;
        case 3: src = w_proj; dst = projT; R = 256;  C = 256;  break;
        default:src = w_d2;   dst = d2T;   R = 256;  C = 256;  break;
    }
    int bx = blockIdx.x * 32, by = blockIdx.y * 32;
    if (bx >= C || by >= R) return;
    __shared__ float t[32][33];
    #pragma unroll
    for (int j = 0; j < 32; j += 8)
        t[threadIdx.y + j][threadIdx.x] =
            src[(size_t)(by + threadIdx.y + j) * C + bx + threadIdx.x];
    __syncthreads();
    #pragma unroll
    for (int j = 0; j < 32; j += 8)
        dst[(size_t)(bx + threadIdx.y + j) * R + by + threadIdx.x] =
            __float2half(t[threadIdx.x][threadIdx.y + j]);
}

// -------------------- LayerNorm (warp per row) ----------------------------
__global__ void __launch_bounds__(256)
ln_kernel(const float* __restrict__ x, const float* __restrict__ g,
          const float* __restrict__ b, __half* __restrict__ out)
{
    int warp = threadIdx.x >> 5, lane = threadIdx.x & 31;
    int row  = blockIdx.x * 8 + warp;
    const float* xr = x + (size_t)row*CH + lane*8;

    float v[8];
    *(float4*)(v)     = *(const float4*)(xr);
    *(float4*)(v + 4) = *(const float4*)(xr + 4);

    float s = 0.f;
    #pragma unroll
    for (int j = 0; j < 8; j++) s += v[j];
    #pragma unroll
    for (int o = 16; o > 0; o >>= 1) s += __shfl_xor_sync(0xffffffffu, s, o);
    float mean = s * (1.0f / CH);

    float d[8], ss = 0.f;
    #pragma unroll
    for (int j = 0; j < 8; j++) { d[j] = v[j] - mean; ss += d[j]*d[j]; }
    #pragma unroll
    for (int o = 16; o > 0; o >>= 1) ss += __shfl_xor_sync(0xffffffffu, ss, o);
    float rstd = rsqrtf(ss * (1.0f / CH) + 1e-5f);

    float gv[8], bv[8];
    *(float4*)(gv)     = *(const float4*)(g + lane*8);
    *(float4*)(gv + 4) = *(const float4*)(g + lane*8 + 4);
    *(float4*)(bv)     = *(const float4*)(b + lane*8);
    *(float4*)(bv + 4) = *(const float4*)(b + lane*8 + 4);

    __half2 o2[4];
    #pragma unroll
    for (int j = 0; j < 4; j++)
        o2[j] = __floats2half2_rn(d[2*j]*rstd*gv[2*j] + bv[2*j],
                                  d[2*j+1]*rstd*gv[2*j+1] + bv[2*j+1]);
    *(uint4*)(out + (size_t)row*CH + lane*8) = *(uint4*)o2;
}

// ----- fp16 tensor-core GEMM (128x128x64, 3-stage, XOR-swizzled smem) -----
__device__ __forceinline__ float gelu_exact(float v) { return v * normcdff(v); }

#define HBM 128
#define HBN 128
#define HBK 64
#define A_HALVES (HBM*HBK)            // 8192 halves = 16 KB
#define STAGE_H  (2*A_HALVES)         // A + B
#define HSMEM_BYTES (3*STAGE_H*2)     // 98304 B (3 stages)

__device__ __forceinline__ void mma16816(float* c, const uint32_t* a,
                                         uint32_t b0, uint32_t b1)
{
    asm volatile(
        "mma.sync.aligned.m16n8k16.row.col.f32.f16.f16.f32 "
        "{%0,%1,%2,%3}, {%4,%5,%6,%7}, {%8,%9}, {%0,%1,%2,%3};"
        : "+f"(c[0]), "+f"(c[1]), "+f"(c[2]), "+f"(c[3])
        : "r"(a[0]), "r"(a[1]), "r"(a[2]), "r"(a[3]), "r"(b0), "r"(b1));
}

template<int EPI, typename OutT>
__global__ void __launch_bounds__(256, 2)
hgemm(const __half* __restrict__ A, const __half* __restrict__ B,
      OutT* __restrict__ C, int M, int N, int K,
      const float* __restrict__ bias, const float* __restrict__ resid)
{
    extern __shared__ __half sh[];

    int tid  = threadIdx.x;
    int lane = tid & 31;
    int warp = tid >> 5;
    int wm   = warp & 1;
    int wn   = warp >> 1;
    int bm   = blockIdx.y * HBM;
    int bn   = blockIdx.x * HBN;

    const __half* Ag = A + (size_t)bm * K;
    const __half* Bg = B + (size_t)bn * K;      // Bt layout [N][K]

    float acc[4][4][4];
    #pragma unroll
    for (int i = 0; i < 4; i++)
        #pragma unroll
        for (int j = 0; j < 4; j++)
            #pragma unroll
            for (int r = 0; r < 4; r++) acc[i][j][r] = 0.f;

    auto issue = [&](int kt, int buf) {
        __half* As = sh + buf * STAGE_H;
        __half* Bs = As + A_HALVES;
        #pragma unroll
        for (int s = 0; s < 4; s++) {
            int c  = tid * 4 + s;               // 0..1023
            int r  = c >> 3, ch = c & 7;
            int sw = ch ^ (r & 7);
            uint32_t da = (uint32_t)__cvta_generic_to_shared(As + r*64 + sw*8);
            const __half* ga = Ag + (size_t)r * K + kt * HBK + ch*8;
            asm volatile("cp.async.cg.shared.global [%0], [%1], 16;\n"
                         :: "r"(da), "l"(ga));
            uint32_t db = (uint32_t)__cvta_generic_to_shared(Bs + r*64 + sw*8);
            const __half* gb = Bg + (size_t)r * K + kt * HBK + ch*8;
            asm volatile("cp.async.cg.shared.global [%0], [%1], 16;\n"
                         :: "r"(db), "l"(gb));
        }
        asm volatile("cp.async.commit_group;\n");
    };

    int nt = K / HBK;                 // 4 (K=256) or 16 (K=1024)
    issue(0, 0);
    issue(1, 1);
    asm volatile("cp.async.wait_group 1;\n");
    __syncthreads();

    for (int kt = 0; kt < nt; kt++) {
        int cur = kt % 3;
        bool more = (kt + 2) < nt;
        if (more) issue(kt + 2, (kt + 2) % 3);

        __half* As = sh + cur * STAGE_H;
        __half* Bs = As + A_HALVES;

        #pragma unroll
        for (int kk = 0; kk < HBK; kk += 16) {
            uint32_t af[4][4];
            #pragma unroll
            for (int i = 0; i < 4; i++) {
                int row   = wm * 64 + i * 16 + (lane & 15);
                int chunk = (kk >> 3) + (lane >> 4);
                uint32_t ad = (uint32_t)__cvta_generic_to_shared(
                    As + row*64 + ((chunk ^ (row & 7)) * 8));
                asm volatile(
                    "ldmatrix.sync.aligned.m8n8.x4.shared.b16 {%0,%1,%2,%3}, [%4];"
                    : "=r"(af[i][0]), "=r"(af[i][1]), "=r"(af[i][2]), "=r"(af[i][3])
                    : "r"(ad));
            }
            #pragma unroll
            for (int j = 0; j < 2; j++) {
                uint32_t bf[4];
                int nrow  = wn * 32 + j * 16 + (lane & 15);
                int chunk = (kk >> 3) + (lane >> 4);
                uint32_t bd = (uint32_t)__cvta_generic_to_shared(
                    Bs + nrow*64 + ((chunk ^ (nrow & 7)) * 8));
                asm volatile(
                    "ldmatrix.sync.aligned.m8n8.x4.shared.b16 {%0,%1,%2,%3}, [%4];"
                    : "=r"(bf[0]), "=r"(bf[1]), "=r"(bf[2]), "=r"(bf[3])
                    : "r"(bd));
                #pragma unroll
                for (int i = 0; i < 4; i++) {
                    mma16816(acc[i][2*j],     af[i], bf[0], bf[2]);
                    mma16816(acc[i][2*j + 1], af[i], bf[1], bf[3]);
                }
            }
        }

        if (more) asm volatile("cp.async.wait_group 1;\n");
        else      asm volatile("cp.async.wait_group 0;\n");
        __syncthreads();
    }

    #pragma unroll
    for (int i = 0; i < 4; i++) {
        int row = bm + wm * 64 + i * 16 + (lane >> 2);
        #pragma unroll
        for (int jj = 0; jj < 4; jj++) {
            int col = bn + wn * 32 + (jj >> 1) * 16 + (jj & 1) * 8 + (lane & 3) * 2;
            float2 v0 = make_float2(acc[i][jj][0], acc[i][jj][1]);
            float2 v1 = make_float2(acc[i][jj][2], acc[i][jj][3]);
            if (EPI >= 1) {
                float2 bv = *(const float2*)&bias[col];
                v0.x += bv.x; v0.y += bv.y;
                v1.x += bv.x; v1.y += bv.y;
            }
            if (EPI == 1) {
                float2 r0 = *(const float2*)&resid[(size_t)row * N + col];
                float2 r1 = *(const float2*)&resid[(size_t)(row + 8) * N + col];
                v0.x += r0.x; v0.y += r0.y;
                v1.x += r1.x; v1.y += r1.y;
            }
            if (EPI == 2) {
                v0.x = gelu_exact(v0.x); v0.y = gelu_exact(v0.y);
                v1.x = gelu_exact(v1.x); v1.y = gelu_exact(v1.y);
            }
            if constexpr (sizeof(OutT) == 2) {
                *(__half2*)&C[(size_t)row * N + col]       = __floats2half2_rn(v0.x, v0.y);
                *(__half2*)&C[(size_t)(row + 8) * N + col] = __floats2half2_rn(v1.x, v1.y);
            } else {
                *(float2*)&C[(size_t)row * N + col]       = v0;
                *(float2*)&C[(size_t)(row + 8) * N + col] = v1;
            }
        }
    }
}

// ===== pe GEMM (128x64x64 XOR-swizzled): s = av + U_h @ w_d2[:, h] ========
// grid (NPTS/128, 4 heads), 8 warps = 4(M) x 2(N), warp tile 32x32.
// A = U rows (stride 1024), B = wd2T rows (stride 256). K=256 -> nt=4.
#define PE_A_HALVES (128*64)              // 8192
#define PE_B_HALVES (64*64)               // 4096
#define PE_STAGE    (PE_A_HALVES + PE_B_HALVES)   // 12288 halves
#define PESMEM_BYTES (3*PE_STAGE*2)       // 73728 B

__global__ void __launch_bounds__(256, 2)
pe_gemm(const __half* __restrict__ U, const __half* __restrict__ wd2T,
        const __half* __restrict__ av, __half* __restrict__ s)
{
    extern __shared__ __half sp[];

    int tid  = threadIdx.x;
    int lane = tid & 31;
    int warp = tid >> 5;
    int wm   = warp >> 1;     // 4 over M
    int wn   = warp & 1;      // 2 over N
    int bm   = blockIdx.x * 128;
    int head = blockIdx.y;

    const __half* Ag = U + (size_t)bm * 1024 + head * 256;
    const __half* Bg = wd2T + (size_t)(head * 64) * 256;

    float acc[2][4][4];
    #pragma unroll
    for (int i = 0; i < 2; i++)
        #pragma unroll
        for (int j = 0; j < 4; j++)
            #pragma unroll
            for (int r = 0; r < 4; r++) acc[i][j][r] = 0.f;

    auto issue = [&](int kt, int buf) {
        __half* As = sp + buf * PE_STAGE;
        __half* Bs = As + PE_A_HALVES;
        #pragma unroll
        for (int q = 0; q < 6; q++) {
            int c = q * 256 + tid;            // 0..1535
            if (c < 1024) {                   // A: 128 rows x 8 chunks
                int r = c >> 3, ch = c & 7;
                int sw = ch ^ (r & 7);
                uint32_t da = (uint32_t)__cvta_generic_to_shared(As + r*64 + sw*8);
                const __half* ga = Ag + (size_t)r * 1024 + kt * 64 + ch*8;
                asm volatile("cp.async.cg.shared.global [%0], [%1], 16;\n"
                             :: "r"(da), "l"(ga));
            } else {                          // B: 64 rows x 8 chunks
                int l = c - 1024;
                int r = l >> 3, ch = l & 7;
                int sw = ch ^ (r & 7);
                uint32_t db = (uint32_t)__cvta_generic_to_shared(Bs + r*64 + sw*8);
                const __half* gb = Bg + (size_t)r * 256 + kt * 64 + ch*8;
                asm volatile("cp.async.cg.shared.global [%0], [%1], 16;\n"
                             :: "r"(db), "l"(gb));
            }
        }
        asm volatile("cp.async.commit_group;\n");
    };

    const int nt = 4;                     // K=256 / 64
    issue(0, 0);
    issue(1, 1);
    asm volatile("cp.async.wait_group 1;\n");
    __syncthreads();

    for (int kt = 0; kt < nt; kt++) {
        int cur = kt % 3;
        bool more = (kt + 2) < nt;
        if (more) issue(kt + 2, (kt + 2) % 3);

        __half* As = sp + cur * PE_STAGE;
        __half* Bs = As + PE_A_HALVES;

        #pragma unroll
        for (int kk = 0; kk < 64; kk += 16) {
            uint32_t af[2][4];
            #pragma unroll
            for (int i = 0; i < 2; i++) {
                int row   = wm * 32 + i * 16 + (lane & 15);
                int chunk = (kk >> 3) + (lane >> 4);
                uint32_t ad = (uint32_t)__cvta_generic_to_shared(
                    As + row*64 + ((chunk ^ (row & 7)) * 8));
                asm volatile(
                    "ldmatrix.sync.aligned.m8n8.x4.shared.b16 {%0,%1,%2,%3}, [%4];"
                    : "=r"(af[i][0]), "=r"(af[i][1]), "=r"(af[i][2]), "=r"(af[i][3])
                    : "r"(ad));
            }
            #pragma unroll
            for (int j = 0; j < 2; j++) {
                uint32_t bf[4];
                int nrow  = wn * 32 + j * 16 + (lane & 15);
                int chunk = (kk >> 3) + (lane >> 4);
                uint32_t bd = (uint32_t)__cvta_generic_to_shared(
                    Bs + nrow*64 + ((chunk ^ (nrow & 7)) * 8));
                asm volatile(
                    "ldmatrix.sync.aligned.m8n8.x4.shared.b16 {%0,%1,%2,%3}, [%4];"
                    : "=r"(bf[0]), "=r"(bf[1]), "=r"(bf[2]), "=r"(bf[3])
                    : "r"(bd));
                #pragma unroll
                for (int i = 0; i < 2; i++) {
                    mma16816(acc[i][2*j],     af[i], bf[0], bf[2]);
                    mma16816(acc[i][2*j + 1], af[i], bf[1], bf[3]);
                }
            }
        }

        if (more) asm volatile("cp.async.wait_group 1;\n");
        else      asm volatile("cp.async.wait_group 0;\n");
        __syncthreads();
    }

    // epilogue: s[row, head*64 + col] = av[...] + acc
    #pragma unroll
    for (int i = 0; i < 2; i++) {
        int row = bm + wm * 32 + i * 16 + (lane >> 2);
        #pragma unroll
        for (int jj = 0; jj < 4; jj++) {
            int col = head * 64 + wn * 32 + (jj >> 1) * 16 + (jj & 1) * 8 + (lane & 3) * 2;
            float2 a0 = __half22float2(*(const __half2*)&av[(size_t)row * CH + col]);
            float2 a1 = __half22float2(*(const __half2*)&av[(size_t)(row + 8) * CH + col]);
            *(__half2*)&s[(size_t)row * CH + col] =
                __floats2half2_rn(a0.x + acc[i][jj][0], a0.y + acc[i][jj][1]);
            *(__half2*)&s[(size_t)(row + 8) * CH + col] =
                __floats2half2_rn(a1.x + acc[i][jj][2], a1.y + acc[i][jj][3]);
        }
    }
}

// -------- KNN attention: warp/point, half2 datapath (R12 best) ------------
__global__ void __launch_bounds__(256, 3)
attn_kernel(const __half* __restrict__ qkv, const int* __restrict__ nns,
            const float* __restrict__ xyz,
            const float* __restrict__ w_d1, const float* __restrict__ b_d1,
            __half* __restrict__ avb, __half* __restrict__ ub)
{
    int lane = threadIdx.x & 31;
    int p    = threadIdx.x >> 5;
    int pi   = blockIdx.x * 8 + p;
    int bb   = pi >> 13;

    int nbr = 0; float rx = 0.f, ry = 0.f;
    if (lane < 16) {
        int j = nns[pi*32 + lane];
        nbr = (bb << 13) + j;
        rx = xyz[pi*2]     - xyz[nbr*2];
        ry = xyz[pi*2 + 1] - xyz[nbr*2 + 1];
    }

    __half2 qf2[4];
    {
        uint4 qv = *(const uint4*)(qkv + (size_t)pi*QKVW + lane*8);
        const __half2* qh = (const __half2*)&qv;
        #pragma unroll
        for (int i = 0; i < 4; i++) qf2[i] = qh[i];
    }

    float attn[16];
    #pragma unroll
    for (int k = 0; k < 16; k++) {
        int rowk = __shfl_sync(0xffffffffu, nbr, k);
        uint4 kv = *(const uint4*)(qkv + (size_t)rowk*QKVW + CH + lane*8);
        const __half2* kh = (const __half2*)&kv;
        __half2 acc2 = __floats2half2_rn(0.f, 0.f);
        #pragma unroll
        for (int i = 0; i < 4; i++) acc2 = __hfma2(qf2[i], kh[i], acc2);
        float2 pf = __half22float2(acc2);
        float pr = pf.x + pf.y;
        pr += __shfl_xor_sync(0xffffffffu, pr, 4);
        pr += __shfl_xor_sync(0xffffffffu, pr, 2);
        pr += __shfl_xor_sync(0xffffffffu, pr, 1);
        attn[k] = pr * 0.125f;
    }

    float mx = -1e30f;
    #pragma unroll
    for (int k = 0; k < 16; k++) mx = fmaxf(mx, attn[k]);
    float sm = 0.f;
    #pragma unroll
    for (int k = 0; k < 16; k++) { attn[k] = __expf(attn[k] - mx); sm += attn[k]; }
    float inv = 1.f / sm;
    #pragma unroll
    for (int k = 0; k < 16; k++) attn[k] *= inv;

    __half2 wx2[4], wy2[4], wb2[4];
    #pragma unroll
    for (int i = 0; i < 4; i++) {
        int c = lane*8 + 2*i;
        wx2[i] = __floats2half2_rn(w_d1[c],      w_d1[c+1]);
        wy2[i] = __floats2half2_rn(w_d1[CH+c],   w_d1[CH+c+1]);
        wb2[i] = __floats2half2_rn(b_d1[c],      b_d1[c+1]);
    }

    const __half2 z2 = __floats2half2_rn(0.f, 0.f);
    float av[8];
    __half2 u2[4][4];
    #pragma unroll
    for (int i = 0; i < 4; i++) {
        av[2*i] = av[2*i+1] = 0.f;
        u2[0][i] = u2[1][i] = u2[2][i] = u2[3][i] = z2;
    }

    #pragma unroll
    for (int k = 0; k < 16; k++) {
        int   rowk = __shfl_sync(0xffffffffu, nbr, k);
        float rxk  = __shfl_sync(0xffffffffu, rx, k);
        float ryk  = __shfl_sync(0xffffffffu, ry, k);
        float ak   = attn[k];
        __half2 a02 = __float2half2_rn(__shfl_sync(0xffffffffu, attn[k], 0));
        __half2 a12 = __float2half2_rn(__shfl_sync(0xffffffffu, attn[k], 8));
        __half2 a22 = __float2half2_rn(__shfl_sync(0xffffffffu, attn[k], 16));
        __half2 a32 = __float2half2_rn(__shfl_sync(0xffffffffu, attn[k], 24));
        __half2 rx2 = __float2half2_rn(rxk);
        __half2 ry2 = __float2half2_rn(ryk);

        uint4 vv = *(const uint4*)(qkv + (size_t)rowk*QKVW + 2*CH + lane*8);
        const __half2* vh = (const __half2*)&vv;
        #pragma unroll
        for (int i = 0; i < 4; i++) {
            __half2 t2 = __hmax2(__hfma2(rx2, wx2[i],
                                 __hfma2(ry2, wy2[i], wb2[i])), z2);
            u2[0][i] = __hfma2(a02, t2, u2[0][i]);
            u2[1][i] = __hfma2(a12, t2, u2[1][i]);
            u2[2][i] = __hfma2(a22, t2, u2[2][i]);
            u2[3][i] = __hfma2(a32, t2, u2[3][i]);
            float2 vf = __half22float2(vh[i]);
            av[2*i]   = fmaf(ak, vf.x, av[2*i]);
            av[2*i+1] = fmaf(ak, vf.y, av[2*i+1]);
        }
    }

    {
        __half2 t4[4];
        #pragma unroll
        for (int i = 0; i < 4; i++)
            t4[i] = __floats2half2_rn(av[2*i], av[2*i+1]);
        *(uint4*)(avb + (size_t)pi*CH + lane*8) = *(uint4*)t4;
    }
    #pragma unroll
    for (int h = 0; h < 4; h++)
        *(uint4*)(ub + (size_t)pi*1024 + h*256 + lane*8) = *(uint4*)(u2[h]);
}

// -------------------- launch ----------------------------------------------
extern "C" void kernel_launch(void* const* d_in, const int* in_sizes, int n_in,
                              void* d_out, int out_size)
{
    const float* xyz      = (const float*)d_in[0];
    const float* xy_embed = (const float*)d_in[1];
    const int*   nns      = (const int*)  d_in[2];
    const float* ln1_g    = (const float*)d_in[3];
    const float* ln1_b    = (const float*)d_in[4];
    const float* w_qkv    = (const float*)d_in[5];
    const float* w_d1     = (const float*)d_in[6];
    const float* b_d1     = (const float*)d_in[7];
    const float* w_d2     = (const float*)d_in[8];
    const float* b_d2     = (const float*)d_in[9];
    const float* w_proj   = (const float*)d_in[10];
    const float* b_proj   = (const float*)d_in[11];
    const float* ln2_g    = (const float*)d_in[12];
    const float* ln2_b    = (const float*)d_in[13];
    const float* w_m1     = (const float*)d_in[14];
    const float* b_m1     = (const float*)d_in[15];
    const float* w_m2     = (const float*)d_in[16];
    const float* b_m2     = (const float*)d_in[17];
    float* out = (float*)d_out;

    __half *h, *qkvh, *avb, *ub, *s16, *mlp1, *wqkvT, *wm1T, *wm2T, *wprojT, *wd2T;
    float *x, *bfold;
    cudaGetSymbolAddress((void**)&h,      g_h);
    cudaGetSymbolAddress((void**)&qkvh,   g_qkvh);
    cudaGetSymbolAddress((void**)&avb,    g_av);
    cudaGetSymbolAddress((void**)&ub,     g_u);
    cudaGetSymbolAddress((void**)&s16,    g_s);
    cudaGetSymbolAddress((void**)&x,      g_x);
    cudaGetSymbolAddress((void**)&mlp1,   g_mlp1);
    cudaGetSymbolAddress((void**)&wqkvT,  g_wqkvT);
    cudaGetSymbolAddress((void**)&wm1T,   g_wm1T);
    cudaGetSymbolAddress((void**)&wm2T,   g_wm2T);
    cudaGetSymbolAddress((void**)&wprojT, g_wprojT);
    cudaGetSymbolAddress((void**)&wd2T,   g_wd2T);
    cudaGetSymbolAddress((void**)&bfold,  g_bfold);

    cudaFuncSetAttribute(hgemm<0, __half>,
        cudaFuncAttributeMaxDynamicSharedMemorySize, HSMEM_BYTES);
    cudaFuncSetAttribute(hgemm<1, float>,
        cudaFuncAttributeMaxDynamicSharedMemorySize, HSMEM_BYTES);
    cudaFuncSetAttribute(hgemm<2, __half>,
        cudaFuncAttributeMaxDynamicSharedMemorySize, HSMEM_BYTES);
    cudaFuncSetAttribute(pe_gemm,
        cudaFuncAttributeMaxDynamicSharedMemorySize, PESMEM_BYTES);

    // 0. prologue: tiled transposes + bfold (one launch)
    prologue_all<<<dim3(32, 32, 6), dim3(32, 8)>>>(
        w_qkv, w_m1, w_m2, w_proj, w_d2, b_d2, b_proj,
        wqkvT, wm1T, wm2T, wprojT, wd2T, bfold);

    // 1. LN1 -> half
    ln_kernel<<<NPTS/8, 256>>>(xy_embed, ln1_g, ln1_b, h);
    // 2. qkv = h @ w_qkv  (N=768, K=256)
    hgemm<0, __half><<<dim3(QKVW/HBN, NPTS/HBM), 256, HSMEM_BYTES>>>(
        h, wqkvT, qkvh, NPTS, QKVW, CH, nullptr, nullptr);
    // 3. KNN attention -> av, U
    attn_kernel<<<NPTS/8, 256>>>(qkvh, nns, xyz, w_d1, b_d1, avb, ub);
    // 3.5 pe: s = av + U_h @ w_d2[:, h-slice]
    pe_gemm<<<dim3(NPTS/128, 4), 256, PESMEM_BYTES>>>(ub, wd2T, avb, s16);
    // 4. x = xy_embed + s @ w_proj + bfold  (N=256, K=256)
    hgemm<1, float><<<dim3(CH/HBN, NPTS/HBM), 256, HSMEM_BYTES>>>(
        s16, wprojT, x, NPTS, CH, CH, bfold, xy_embed);
    // 5. LN2 -> half
    ln_kernel<<<NPTS/8, 256>>>(x, ln2_g, ln2_b, h);
    // 6. mlp1 = gelu(h @ w_m1 + b_m1)  (N=1024, K=256)
    hgemm<2, __half><<<dim3(1024/HBN, NPTS/HBM), 256, HSMEM_BYTES>>>(
        h, wm1T, mlp1, NPTS, 1024, CH, b_m1, nullptr);
    // 7. out = x + mlp1 @ w_m2 + b_m2  (N=256, K=1024)
    hgemm<1, float><<<dim3(CH/HBN, NPTS/HBM), 256, HSMEM_BYTES>>>(
        mlp1, wm2T, out, NPTS, CH, 1024, b_m2, x);
}